// round 2
// baseline (speedup 1.0000x reference)
#include <cuda_runtime.h>
#include <math.h>
#include <stdint.h>

// ---------------- constants ----------------
#define NB      64        // combined batch: 0..31 = x, 32..63 = -x
#define NPATCH  16
#define PATCH   32
#define DMODEL  1024
#define NH      16
#define HDIM    64
#define NDFF    4096
#define NLAYER  8
#define CMAX    20        // max kv cache length (16 prefill + 4 AR)
#define T1      1024      // prefill tokens = 64 * 16
#define T2      256       // AR tokens = 64 * 4
#define EPSF    1e-6f

// ---------------- device scratch (static, no allocation) ----------------
__device__ float g_normed[T1 * PATCH];
__device__ float g_anorm [T2 * PATCH];
__device__ float g_ctxmu [NB * NPATCH];
__device__ float g_ctxsg [NB * NPATCH];
__device__ float g_nmu   [NB * 4];
__device__ float g_nsg   [NB * 4];
__device__ int   g_ispos [32];
__device__ float g_hdd [T1 * DMODEL];
__device__ float g_xn  [T1 * DMODEL];
__device__ float g_qkv [T1 * 3 * DMODEL];
__device__ float g_attb[T1 * DMODEL];
__device__ float g_h1  [T1 * NDFF];
__device__ float g_Kc  [NLAYER * NB * CMAX * DMODEL];
__device__ float g_Vc  [NLAYER * NB * CMAX * DMODEL];
__device__ float g_no1 [NB * 128];
__device__ float g_no2 [NB * 128];
__device__ float g_last[NB * 128];

// ---------------- helpers ----------------
__device__ __forceinline__ float warpSum(float v) {
#pragma unroll
    for (int o = 16; o; o >>= 1) v += __shfl_xor_sync(0xffffffffu, v, o);
    return v;
}

__device__ __forceinline__ float gelu_tanh(float x) {
    float x3 = x * x * x;
    return 0.5f * x * (1.0f + tanhf(0.7978845608028654f * (x + 0.044715f * x3)));
}

__device__ __forceinline__ float tf32_rna(float f) {
    uint32_t u;
    asm("cvt.rna.tf32.f32 %0, %1;" : "=r"(u) : "f"(f));
    return __uint_as_float(u);
}

// ---------------- running stats ----------------
__global__ void stats_kernel(const float* __restrict__ x) {
    int b = blockIdx.x, lane = threadIdx.x;
    const float* xb = x + (size_t)(b & 31) * 512;
    float sign = (b < 32) ? 1.f : -1.f;
    if (b < 32) {
        bool ok = true;
        for (int i = lane; i < 512; i += 32) ok = ok && (xb[i] >= 0.f);
        unsigned bal = __ballot_sync(0xffffffffu, ok);
        if (lane == 0) g_ispos[b] = (bal == 0xffffffffu) ? 1 : 0;
    }
    float n = 0.f, mu = 0.f, sg = 0.f;
    for (int p = 0; p < NPATCH; p++) {
        float v = sign * xb[p * PATCH + lane];
        float s = warpSum(v);
        float nn = n + 32.f;
        float nmu = (n * mu + s) / nn;
        float m2 = n * sg * sg + warpSum((v - mu) * (v - nmu));
        float nsg = sqrtf(fmaxf(m2 / nn, 1e-12f));
        n = nn; mu = nmu; sg = nsg;
        if (lane == 0) { g_ctxmu[b * NPATCH + p] = mu; g_ctxsg[b * NPATCH + p] = sg; }
        g_normed[(b * NPATCH + p) * PATCH + lane] = (v - mu) / (sg + EPSF);
    }
}

__global__ void ar_stats_kernel() {
    int b = blockIdx.x, lane = threadIdx.x;
    float n = 512.f, mu = g_ctxmu[b * NPATCH + 15], sg = g_ctxsg[b * NPATCH + 15];
    for (int p = 0; p < 4; p++) {
        float v = g_last[b * 128 + p * PATCH + lane];
        float s = warpSum(v);
        float nn = n + 32.f;
        float nmu = (n * mu + s) / nn;
        float m2 = n * sg * sg + warpSum((v - mu) * (v - nmu));
        float ns = sqrtf(fmaxf(m2 / nn, 1e-12f));
        n = nn; mu = nmu; sg = ns;
        if (lane == 0) { g_nmu[b * 4 + p] = mu; g_nsg[b * 4 + p] = sg; }
        g_anorm[(b * 4 + p) * PATCH + lane] = (v - mu) / (sg + EPSF);
    }
}

// ---------------- layernorm ----------------
__global__ void ln_kernel(const float* __restrict__ in, const float* __restrict__ sc,
                          float* __restrict__ out) {
    __shared__ float row[DMODEL];
    __shared__ float red[8];
    __shared__ float s_mean, s_inv;
    int r = blockIdx.x, tid = threadIdx.x;
    const float* xr = in + (size_t)r * DMODEL;
    float ls = 0.f;
    for (int c = tid; c < DMODEL; c += 256) { float v = xr[c]; row[c] = v; ls += v; }
    ls = warpSum(ls);
    if ((tid & 31) == 0) red[tid >> 5] = ls;
    __syncthreads();
    if (tid < 8) {
        float t = red[tid];
#pragma unroll
        for (int o = 4; o; o >>= 1) t += __shfl_xor_sync(0xffu, t, o);
        if (tid == 0) s_mean = t / (float)DMODEL;
    }
    __syncthreads();
    float m = s_mean;
    float lv = 0.f;
    for (int c = tid; c < DMODEL; c += 256) { float d = row[c] - m; lv += d * d; }
    lv = warpSum(lv);
    if ((tid & 31) == 0) red[tid >> 5] = lv;
    __syncthreads();
    if (tid < 8) {
        float t = red[tid];
#pragma unroll
        for (int o = 4; o; o >>= 1) t += __shfl_xor_sync(0xffu, t, o);
        if (tid == 0) s_inv = rsqrtf(t / (float)DMODEL + EPSF);
    }
    __syncthreads();
    float inv = s_inv;
    for (int c = tid; c < DMODEL; c += 256)
        out[(size_t)r * DMODEL + c] = (row[c] - m) * inv * sc[c];
}

// ================= TF32 tensor-core GEMM (3xTF32 split, fp32 accuracy) ======
// C[M,N] = A[M,K] * B[K,N], all dense row-major; M%BM==0, N%BN==0, K%32==0.
// flags: 1 = C += result, 2 = gelu(result)
#define MMA_TF32(d, a, b)                                                       \
    asm volatile(                                                               \
        "mma.sync.aligned.m16n8k8.row.col.f32.tf32.tf32.f32 "                   \
        "{%0,%1,%2,%3},{%4,%5,%6,%7},{%8,%9},{%0,%1,%2,%3};"                    \
        : "+f"((d)[0]), "+f"((d)[1]), "+f"((d)[2]), "+f"((d)[3])                \
        : "r"((a)[0]), "r"((a)[1]), "r"((a)[2]), "r"((a)[3]),                   \
          "r"((b)[0]), "r"((b)[1]))

#define GK   32          // K tile
#define SKW  36          // smem stride (GK + 4): bank = 4*gid + tig, conflict-free frags

template<int BM, int BN>
__global__ void __launch_bounds__(256) tf32_gemm_kernel(
        const float* __restrict__ A, const float* __restrict__ B,
        float* __restrict__ C, int M, int N, int K, int flags) {
    extern __shared__ float sm[];
    float* Ah = sm;                 // [BM][SKW]
    float* Al = Ah + BM * SKW;
    float* Bh = Al + BM * SKW;      // [BN][SKW]  ([n][k] layout)
    float* Bl = Bh + BN * SKW;

    const int tid  = threadIdx.x;
    const int lane = tid & 31;
    const int gid  = lane >> 2;
    const int tig  = lane & 3;
    const int warp = tid >> 5;
    constexpr int WARPS_M = BM / 32;            // 4 or 2
    constexpr int WARPS_N = 8 / WARPS_M;        // 2 or 4
    constexpr int WN = BN / WARPS_N;            // 64 or 32
    constexpr int NT = WN / 8;                  // 8 or 4
    const int warp_m = warp % WARPS_M;
    const int warp_n = warp / WARPS_M;
    const int mBase = warp_m * 32;
    const int nBase = warp_n * WN;
    const int blockRow = blockIdx.y * BM;
    const int blockCol = blockIdx.x * BN;

    float acc[2][NT][4];
#pragma unroll
    for (int i = 0; i < 2; i++)
#pragma unroll
        for (int j = 0; j < NT; j++)
#pragma unroll
            for (int q = 0; q < 4; q++) acc[i][j][q] = 0.f;

    constexpr int A_F4 = BM * GK / 4 / 256;     // float4 per thread for A tile
    constexpr int B_F4 = GK * BN / 4 / 256;

    for (int kk = 0; kk < K; kk += GK) {
        // -- A tile: BM x 32, global [m][k] -> smem [m][k] (hi/lo split)
#pragma unroll
        for (int i = 0; i < A_F4; i++) {
            int id = tid + i * 256;
            int row = id >> 3;           // 8 float4 per 32-float row
            int c   = (id & 7) * 4;
            float4 v = *(const float4*)(A + (size_t)(blockRow + row) * K + kk + c);
            float f[4] = {v.x, v.y, v.z, v.w};
#pragma unroll
            for (int j = 0; j < 4; j++) {
                float hi = tf32_rna(f[j]);
                Ah[row * SKW + c + j] = hi;
                Al[row * SKW + c + j] = f[j] - hi;
            }
        }
        // -- B tile: 32 x BN, global [k][n] -> smem [n][k] (transposed, hi/lo)
#pragma unroll
        for (int i = 0; i < B_F4; i++) {
            int id = tid + i * 256;
            int kr = id / (BN / 4);
            int c  = (id % (BN / 4)) * 4;
            float4 v = *(const float4*)(B + (size_t)(kk + kr) * N + blockCol + c);
            float f[4] = {v.x, v.y, v.z, v.w};
#pragma unroll
            for (int j = 0; j < 4; j++) {
                float hi = tf32_rna(f[j]);
                Bh[(c + j) * SKW + kr] = hi;
                Bl[(c + j) * SKW + kr] = f[j] - hi;
            }
        }
        __syncthreads();

#pragma unroll
        for (int ks = 0; ks < GK / 8; ks++) {
            const int k0 = ks * 8;
            uint32_t ah[2][4], al[2][4];
#pragma unroll
            for (int mt = 0; mt < 2; mt++) {
                int m = mBase + mt * 16;
                ah[mt][0] = __float_as_uint(Ah[(m + gid)     * SKW + k0 + tig]);
                ah[mt][1] = __float_as_uint(Ah[(m + gid + 8) * SKW + k0 + tig]);
                ah[mt][2] = __float_as_uint(Ah[(m + gid)     * SKW + k0 + tig + 4]);
                ah[mt][3] = __float_as_uint(Ah[(m + gid + 8) * SKW + k0 + tig + 4]);
                al[mt][0] = __float_as_uint(Al[(m + gid)     * SKW + k0 + tig]);
                al[mt][1] = __float_as_uint(Al[(m + gid + 8) * SKW + k0 + tig]);
                al[mt][2] = __float_as_uint(Al[(m + gid)     * SKW + k0 + tig + 4]);
                al[mt][3] = __float_as_uint(Al[(m + gid + 8) * SKW + k0 + tig + 4]);
            }
#pragma unroll
            for (int nt = 0; nt < NT; nt++) {
                int n = nBase + nt * 8;
                uint32_t bh[2], bl[2];
                bh[0] = __float_as_uint(Bh[(n + gid) * SKW + k0 + tig]);
                bh[1] = __float_as_uint(Bh[(n + gid) * SKW + k0 + tig + 4]);
                bl[0] = __float_as_uint(Bl[(n + gid) * SKW + k0 + tig]);
                bl[1] = __float_as_uint(Bl[(n + gid) * SKW + k0 + tig + 4]);
#pragma unroll
                for (int mt = 0; mt < 2; mt++) {
                    MMA_TF32(acc[mt][nt], ah[mt], bh);
                    MMA_TF32(acc[mt][nt], al[mt], bh);
                    MMA_TF32(acc[mt][nt], ah[mt], bl);
                }
            }
        }
        __syncthreads();
    }

    // -- epilogue
#pragma unroll
    for (int mt = 0; mt < 2; mt++) {
#pragma unroll
        for (int nt = 0; nt < NT; nt++) {
            int r = blockRow + mBase + mt * 16 + gid;
            int c = blockCol + nBase + nt * 8 + tig * 2;
            float* a = acc[mt][nt];
#pragma unroll
            for (int h = 0; h < 2; h++) {
                size_t o = (size_t)(r + h * 8) * N + c;
                float v0 = a[h * 2 + 0], v1 = a[h * 2 + 1];
                if (flags & 2) { v0 = gelu_tanh(v0); v1 = gelu_tanh(v1); }
                if (flags & 1) { C[o] += v0; C[o + 1] += v1; }
                else           { C[o]  = v0; C[o + 1]  = v1; }
            }
        }
    }
}

static void launch_tf32(const float* A, const float* B, float* C,
                        int M, int N, int K, int flags) {
    if (N >= 2048) {
        constexpr int SMB = (2 * 128 + 2 * 128) * SKW * 4;
        cudaFuncSetAttribute(tf32_gemm_kernel<128, 128>,
                             cudaFuncAttributeMaxDynamicSharedMemorySize, SMB);
        dim3 grid(N / 128, M / 128);
        tf32_gemm_kernel<128, 128><<<grid, 256, SMB>>>(A, B, C, M, N, K, flags);
    } else {
        constexpr int SMB = (2 * 64 + 2 * 128) * SKW * 4;
        cudaFuncSetAttribute(tf32_gemm_kernel<64, 128>,
                             cudaFuncAttributeMaxDynamicSharedMemorySize, SMB);
        dim3 grid(N / 128, M / 64);
        tf32_gemm_kernel<64, 128><<<grid, 256, SMB>>>(A, B, C, M, N, K, flags);
    }
}

// ---------------- generic tiled fp32 GEMM (small/odd shapes only) ----------
#define BM 64
#define BN 64
#define BKK 16
__global__ void gemm_kernel(const float* __restrict__ A, const float* __restrict__ B,
                            const float* __restrict__ bias, float* __restrict__ C,
                            int M, int N, int K,
                            int lda, int aRowStart, int aRowStep,
                            int ldb, int bColStart, int bColStep,
                            int ldc, int flags) {
    __shared__ float As[BKK][BM + 4];
    __shared__ float Bs[BKK][BN + 4];
    int tid = threadIdx.y * 16 + threadIdx.x;
    int rowBase = blockIdx.y * BM;
    int colBase = blockIdx.x * BN;
    int r0 = threadIdx.y * 4, c0 = threadIdx.x * 4;
    float acc[4][4] = {};
    int aRow = tid >> 2;
    int aK   = (tid & 3) * 4;
    int bRow = tid >> 4;
    int bCol = (tid & 15) * 4;

    for (int kk = 0; kk < K; kk += BKK) {
        {
            int gr = rowBase + aRow;
            float4 v = make_float4(0.f, 0.f, 0.f, 0.f);
            if (gr < M) {
                const float* src = A + (size_t)(aRowStart + gr * aRowStep) * lda + kk + aK;
                v = *(const float4*)src;
            }
            As[aK + 0][aRow] = v.x; As[aK + 1][aRow] = v.y;
            As[aK + 2][aRow] = v.z; As[aK + 3][aRow] = v.w;
        }
        {
            int gc = colBase + bCol;
            if (bColStep == 1) {
                float4 v = make_float4(0.f, 0.f, 0.f, 0.f);
                if (gc < N) {
                    const float* src = B + (size_t)(kk + bRow) * ldb + bColStart + gc;
                    v = *(const float4*)src;
                }
                Bs[bRow][bCol + 0] = v.x; Bs[bRow][bCol + 1] = v.y;
                Bs[bRow][bCol + 2] = v.z; Bs[bRow][bCol + 3] = v.w;
            } else {
#pragma unroll
                for (int j = 0; j < 4; j++) {
                    int c = gc + j;
                    Bs[bRow][bCol + j] = (c < N)
                        ? B[(size_t)(kk + bRow) * ldb + bColStart + c * bColStep] : 0.f;
                }
            }
        }
        __syncthreads();
#pragma unroll
        for (int k = 0; k < BKK; k++) {
            float a[4], bb[4];
#pragma unroll
            for (int i = 0; i < 4; i++) a[i] = As[k][r0 + i];
#pragma unroll
            for (int j = 0; j < 4; j++) bb[j] = Bs[k][c0 + j];
#pragma unroll
            for (int i = 0; i < 4; i++)
#pragma unroll
                for (int j = 0; j < 4; j++) acc[i][j] += a[i] * bb[j];
        }
        __syncthreads();
    }
#pragma unroll
    for (int i = 0; i < 4; i++) {
        int r = rowBase + r0 + i;
        if (r >= M) continue;
#pragma unroll
        for (int j = 0; j < 4; j++) {
            int c = colBase + c0 + j;
            if (c >= N) continue;
            float v = acc[i][j];
            if (flags & 4) v += bias[c];
            if (flags & 2) v = gelu_tanh(v);
            size_t o = (size_t)r * ldc + c;
            if (flags & 1) C[o] += v; else C[o] = v;
        }
    }
}

static void launch_gemm(const float* A, const float* B, const float* bias, float* C,
                        int M, int N, int K,
                        int lda, int ars, int arstep,
                        int ldb, int bcs, int bcstep,
                        int ldc, int flags) {
    dim3 grid((N + BN - 1) / BN, (M + BM - 1) / BM), block(16, 16);
    gemm_kernel<<<grid, block>>>(A, B, bias, C, M, N, K, lda, ars, arstep,
                                 ldb, bcs, bcstep, ldc, flags);
}

// ---------------- KV cache append ----------------
__global__ void copy_kv_kernel(const float* __restrict__ qkv, float* __restrict__ Kc,
                               float* __restrict__ Vc, int N, int off) {
    int t = blockIdx.x; int b = t / N, n = t % N;
    size_t dst = ((size_t)b * CMAX + off + n) * DMODEL;
    size_t src = (size_t)t * 3 * DMODEL;
    for (int c = threadIdx.x; c < DMODEL; c += blockDim.x) {
        Kc[dst + c] = qkv[src + DMODEL + c];
        Vc[dst + c] = qkv[src + 2 * DMODEL + c];
    }
}

// ---------------- attention: one warp per (b,h,query) ----------------
__global__ void attn_kernel(const float* __restrict__ qkv, const float* __restrict__ Kc,
                            const float* __restrict__ Vc, float* __restrict__ out,
                            int N, int C, int off) {
    int bh = blockIdx.x; int b = bh / NH, h = bh % NH;
    int n = threadIdx.y, lane = threadIdx.x;
    int t = b * N + n;
    const float* q = qkv + (size_t)t * 3 * DMODEL + h * HDIM;
    int lim = n + off;
    float s = -1e30f;
    if (lane < C && lane <= lim) {
        const float* kr = Kc + ((size_t)b * CMAX + lane) * DMODEL + h * HDIM;
        float d = 0.f;
#pragma unroll
        for (int i = 0; i < HDIM; i++) d += q[i] * kr[i];
        s = d * 0.125f;
    }
    float mx = s;
#pragma unroll
    for (int o = 16; o; o >>= 1) mx = fmaxf(mx, __shfl_xor_sync(0xffffffffu, mx, o));
    float p = (lane < C && lane <= lim) ? expf(s - mx) : 0.f;
    float sum = warpSum(p);
    float a0 = 0.f, a1 = 0.f;
    int mmax = min(lim, C - 1);
    for (int m = 0; m <= mmax; m++) {
        float pm = __shfl_sync(0xffffffffu, p, m);
        const float* vr = Vc + ((size_t)b * CMAX + m) * DMODEL + h * HDIM;
        a0 += pm * vr[lane];
        a1 += pm * vr[lane + 32];
    }
    float inv = 1.f / sum;
    out[(size_t)t * DMODEL + h * HDIM + lane]      = a0 * inv;
    out[(size_t)t * DMODEL + h * HDIM + lane + 32] = a1 * inv;
}

// ---------------- epilogue kernels ----------------
__global__ void revin_last_kernel() {
    int b = blockIdx.x, o = threadIdx.x;
    g_last[b * 128 + o] = g_no1[b * 128 + o] * (g_ctxsg[b * NPATCH + 15] + EPSF)
                        + g_ctxmu[b * NPATCH + 15];
}

__global__ void assemble_kernel(float* __restrict__ out) {
    int idx = blockIdx.x * blockDim.x + threadIdx.x;
    int b = idx / 256, t = idx % 256;
    float m;
    if (t < 128) {
        m = 0.5f * (g_last[b * 128 + t] - g_last[(b + 32) * 128 + t]);
    } else {
        int o = t - 128;
        float va = g_no2[b * 128 + o]        * (g_nsg[b * 4 + 3] + EPSF)        + g_nmu[b * 4 + 3];
        float vb = g_no2[(b + 32) * 128 + o] * (g_nsg[(b + 32) * 4 + 3] + EPSF) + g_nmu[(b + 32) * 4 + 3];
        m = 0.5f * (va - vb);
    }
    if (g_ispos[b]) m = fmaxf(m, 0.f);
    out[idx] = m;
}

// ---------------- full transformer forward ----------------
static void model_fwd_host(int T, int N, int C, int off,
                           const float* in_tok,
                           const float* W_in, const float* b_in, const float* ln1,
                           const float* Wqkv, const float* Wo, const float* ln2,
                           const float* W1, const float* W2, const float* lnf,
                           const float* Wout,
                           float* hdd, float* xn, float* qkv, float* att, float* h1,
                           float* Kc, float* Vc,
                           float* nosel, int selStart, int selStep) {
    // embed: feat @ W_in (mask half is zero -> first 32 rows only) + b_in
    launch_gemm(in_tok, W_in, b_in, hdd, T, DMODEL, PATCH,
                PATCH, 0, 1, DMODEL, 0, 1, DMODEL, 4);
    for (int l = 0; l < NLAYER; l++) {
        ln_kernel<<<T, 256>>>(hdd, ln1 + (size_t)l * DMODEL, xn);
        launch_tf32(xn, Wqkv + (size_t)l * DMODEL * 3 * DMODEL, qkv,
                    T, 3 * DMODEL, DMODEL, 0);
        float* Kl = Kc + (size_t)l * NB * CMAX * DMODEL;
        float* Vl = Vc + (size_t)l * NB * CMAX * DMODEL;
        copy_kv_kernel<<<T, 256>>>(qkv, Kl, Vl, N, off);
        attn_kernel<<<NB * NH, dim3(32, N)>>>(qkv, Kl, Vl, att, N, C, off);
        launch_tf32(att, Wo + (size_t)l * DMODEL * DMODEL, hdd,
                    T, DMODEL, DMODEL, 1);
        ln_kernel<<<T, 256>>>(hdd, ln2 + (size_t)l * DMODEL, xn);
        launch_tf32(xn, W1 + (size_t)l * DMODEL * NDFF, h1,
                    T, NDFF, DMODEL, 2);
        launch_tf32(h1, W2 + (size_t)l * NDFF * DMODEL, hdd,
                    T, DMODEL, NDFF, 1);
    }
    ln_kernel<<<T, 256>>>(hdd, lnf, xn);
    // Wout, channel-5 columns only (cols o*10+5), last token of each batch row
    launch_gemm(xn, Wout, nullptr, nosel, NB, 128, DMODEL,
                DMODEL, selStart, selStep, 1280, 5, 10, 128, 0);
}

// ---------------- entry ----------------
extern "C" void kernel_launch(void* const* d_in, const int* in_sizes, int n_in,
                              void* d_out, int out_size) {
    const float* x     = (const float*)d_in[0];
    const float* W_in  = (const float*)d_in[1];
    const float* b_in  = (const float*)d_in[2];
    const float* ln1_s = (const float*)d_in[3];
    const float* Wqkv  = (const float*)d_in[4];
    const float* Wo    = (const float*)d_in[5];
    const float* ln2_s = (const float*)d_in[6];
    const float* W1    = (const float*)d_in[7];
    const float* W2    = (const float*)d_in[8];
    const float* lnf_s = (const float*)d_in[9];
    const float* Wout  = (const float*)d_in[10];
    // d_in[11] = Wqs: unused for the median output (channel 5)

    float *normed, *anorm, *hdd, *xn, *qkv, *att, *h1, *Kc, *Vc, *no1, *no2;
    cudaGetSymbolAddress((void**)&normed, g_normed);
    cudaGetSymbolAddress((void**)&anorm,  g_anorm);
    cudaGetSymbolAddress((void**)&hdd,    g_hdd);
    cudaGetSymbolAddress((void**)&xn,     g_xn);
    cudaGetSymbolAddress((void**)&qkv,    g_qkv);
    cudaGetSymbolAddress((void**)&att,    g_attb);
    cudaGetSymbolAddress((void**)&h1,     g_h1);
    cudaGetSymbolAddress((void**)&Kc,     g_Kc);
    cudaGetSymbolAddress((void**)&Vc,     g_Vc);
    cudaGetSymbolAddress((void**)&no1,    g_no1);
    cudaGetSymbolAddress((void**)&no2,    g_no2);

    // Stage A: running stats + normalization for x and -x (batch 64)
    stats_kernel<<<NB, 32>>>(x);

    // Stage B: prefill, 16 patches/batch, cache offset 0, C=16
    model_fwd_host(T1, NPATCH, 16, 0, normed,
                   W_in, b_in, ln1_s, Wqkv, Wo, ln2_s, W1, W2, lnf_s, Wout,
                   hdd, xn, qkv, att, h1, Kc, Vc,
                   no1, /*selStart=*/15, /*selStep=*/16);
    revin_last_kernel<<<NB, 128>>>();

    // Stage C: AR stats + 1 autoregressive step (4 patches, cache 16..19, C=20)
    ar_stats_kernel<<<NB, 32>>>();
    model_fwd_host(T2, 4, 20, 16, anorm,
                   W_in, b_in, ln1_s, Wqkv, Wo, ln2_s, W1, W2, lnf_s, Wout,
                   hdd, xn, qkv, att, h1, Kc, Vc,
                   no2, /*selStart=*/3, /*selStep=*/4);

    // Stage D: combine x / -x passes, clamp, write [32,256]
    assemble_kernel<<<32, 256>>>((float*)d_out);
}

// round 3
// speedup vs baseline: 3.0140x; 3.0140x over previous
#include <cuda_runtime.h>
#include <cuda_bf16.h>
#include <math.h>
#include <stdint.h>

// ---------------- constants ----------------
#define NB      64
#define NPATCH  16
#define PATCH   32
#define DMODEL  1024
#define NH      16
#define HDIM    64
#define NDFF    4096
#define NLAYER  8
#define CMAX    20
#define T1      1024
#define T2      256
#define EPSF    1e-6f

// ---------------- device scratch ----------------
__device__ float g_normed[T1 * PATCH];
__device__ float g_anorm [T2 * PATCH];
__device__ float g_ctxmu [NB * NPATCH];
__device__ float g_ctxsg [NB * NPATCH];
__device__ float g_nmu   [NB * 4];
__device__ float g_nsg   [NB * 4];
__device__ int   g_ispos [32];
__device__ float g_hdd [T1 * DMODEL];
__device__ float g_xn  [T1 * DMODEL];          // fp32 (lnf only)
__device__ float g_qkv [T1 * 3 * DMODEL];
__device__ float g_Kc  [NLAYER * NB * CMAX * DMODEL];
__device__ float g_Vc  [NLAYER * NB * CMAX * DMODEL];
__device__ float g_no1 [NB * 128];
__device__ float g_no2 [NB * 128];
__device__ float g_last[NB * 128];

// bf16 hi/lo activation buffers
__device__ __nv_bfloat16 g_xnh [T1 * DMODEL], g_xnl [T1 * DMODEL];
__device__ __nv_bfloat16 g_atth[T1 * DMODEL], g_attl[T1 * DMODEL];
__device__ __nv_bfloat16 g_h1h [T1 * NDFF],   g_h1l [T1 * NDFF];

// transposed bf16 hi/lo weights: [L][N][K]
__device__ __nv_bfloat16 g_Wqkvh[(size_t)NLAYER * 3072 * 1024];
__device__ __nv_bfloat16 g_Wqkvl[(size_t)NLAYER * 3072 * 1024];
__device__ __nv_bfloat16 g_Woh [(size_t)NLAYER * 1024 * 1024];
__device__ __nv_bfloat16 g_Wol [(size_t)NLAYER * 1024 * 1024];
__device__ __nv_bfloat16 g_W1h [(size_t)NLAYER * 4096 * 1024];
__device__ __nv_bfloat16 g_W1l [(size_t)NLAYER * 4096 * 1024];
__device__ __nv_bfloat16 g_W2h [(size_t)NLAYER * 1024 * 4096];
__device__ __nv_bfloat16 g_W2l [(size_t)NLAYER * 1024 * 4096];

// ---------------- helpers ----------------
__device__ __forceinline__ float warpSum(float v) {
#pragma unroll
    for (int o = 16; o; o >>= 1) v += __shfl_xor_sync(0xffffffffu, v, o);
    return v;
}

__device__ __forceinline__ float gelu_tanh(float x) {
    float x3 = x * x * x;
    return 0.5f * x * (1.0f + tanhf(0.7978845608028654f * (x + 0.044715f * x3)));
}

__device__ __forceinline__ void split_bf16(float v, __nv_bfloat16& h, __nv_bfloat16& l) {
    h = __float2bfloat16(v);
    l = __float2bfloat16(v - __bfloat162float(h));
}

// ---------------- weight transpose + bf16 split ----------------
// W [L][K][N] fp32 -> Th,Tl [L][N][K] bf16
__global__ void convT_kernel(const float* __restrict__ W,
                             __nv_bfloat16* __restrict__ Th,
                             __nv_bfloat16* __restrict__ Tl, int K, int N) {
    __shared__ float t[32][33];
    int l = blockIdx.z;
    const float* Wl = W + (size_t)l * K * N;
    __nv_bfloat16* Thl = Th + (size_t)l * K * N;
    __nv_bfloat16* Tll = Tl + (size_t)l * K * N;
    int n0 = blockIdx.x * 32, k0 = blockIdx.y * 32;
#pragma unroll
    for (int i = 0; i < 4; i++)
        t[threadIdx.y + 8 * i][threadIdx.x] =
            Wl[(size_t)(k0 + threadIdx.y + 8 * i) * N + n0 + threadIdx.x];
    __syncthreads();
#pragma unroll
    for (int i = 0; i < 4; i++) {
        int n = threadIdx.y + 8 * i;
        float v = t[threadIdx.x][n];
        __nv_bfloat16 h, lo; split_bf16(v, h, lo);
        size_t o = (size_t)(n0 + n) * K + k0 + threadIdx.x;
        Thl[o] = h; Tll[o] = lo;
    }
}

// ---------------- running stats ----------------
__global__ void stats_kernel(const float* __restrict__ x) {
    int b = blockIdx.x, lane = threadIdx.x;
    const float* xb = x + (size_t)(b & 31) * 512;
    float sign = (b < 32) ? 1.f : -1.f;
    if (b < 32) {
        bool ok = true;
        for (int i = lane; i < 512; i += 32) ok = ok && (xb[i] >= 0.f);
        unsigned bal = __ballot_sync(0xffffffffu, ok);
        if (lane == 0) g_ispos[b] = (bal == 0xffffffffu) ? 1 : 0;
    }
    float n = 0.f, mu = 0.f, sg = 0.f;
    for (int p = 0; p < NPATCH; p++) {
        float v = sign * xb[p * PATCH + lane];
        float s = warpSum(v);
        float nn = n + 32.f;
        float nmu = (n * mu + s) / nn;
        float m2 = n * sg * sg + warpSum((v - mu) * (v - nmu));
        float nsg = sqrtf(fmaxf(m2 / nn, 1e-12f));
        n = nn; mu = nmu; sg = nsg;
        if (lane == 0) { g_ctxmu[b * NPATCH + p] = mu; g_ctxsg[b * NPATCH + p] = sg; }
        g_normed[(b * NPATCH + p) * PATCH + lane] = (v - mu) / (sg + EPSF);
    }
}

__global__ void ar_stats_kernel() {
    int b = blockIdx.x, lane = threadIdx.x;
    float n = 512.f, mu = g_ctxmu[b * NPATCH + 15], sg = g_ctxsg[b * NPATCH + 15];
    for (int p = 0; p < 4; p++) {
        float v = g_last[b * 128 + p * PATCH + lane];
        float s = warpSum(v);
        float nn = n + 32.f;
        float nmu = (n * mu + s) / nn;
        float m2 = n * sg * sg + warpSum((v - mu) * (v - nmu));
        float ns = sqrtf(fmaxf(m2 / nn, 1e-12f));
        n = nn; mu = nmu; sg = ns;
        if (lane == 0) { g_nmu[b * 4 + p] = mu; g_nsg[b * 4 + p] = ns; }
        g_anorm[(b * 4 + p) * PATCH + lane] = (v - mu) / (sg + EPSF);
    }
}

// ---------------- layernorm (fp32 out, lnf only) ----------------
__global__ void ln_kernel(const float* __restrict__ in, const float* __restrict__ sc,
                          float* __restrict__ out) {
    __shared__ float row[DMODEL];
    __shared__ float red[8];
    __shared__ float s_mean, s_inv;
    int r = blockIdx.x, tid = threadIdx.x;
    const float* xr = in + (size_t)r * DMODEL;
    float ls = 0.f;
    for (int c = tid; c < DMODEL; c += 256) { float v = xr[c]; row[c] = v; ls += v; }
    ls = warpSum(ls);
    if ((tid & 31) == 0) red[tid >> 5] = ls;
    __syncthreads();
    if (tid < 8) {
        float t = red[tid];
#pragma unroll
        for (int o = 4; o; o >>= 1) t += __shfl_xor_sync(0xffu, t, o);
        if (tid == 0) s_mean = t / (float)DMODEL;
    }
    __syncthreads();
    float m = s_mean;
    float lv = 0.f;
    for (int c = tid; c < DMODEL; c += 256) { float d = row[c] - m; lv += d * d; }
    lv = warpSum(lv);
    if ((tid & 31) == 0) red[tid >> 5] = lv;
    __syncthreads();
    if (tid < 8) {
        float t = red[tid];
#pragma unroll
        for (int o = 4; o; o >>= 1) t += __shfl_xor_sync(0xffu, t, o);
        if (tid == 0) s_inv = rsqrtf(t / (float)DMODEL + EPSF);
    }
    __syncthreads();
    float inv = s_inv;
    for (int c = tid; c < DMODEL; c += 256)
        out[(size_t)r * DMODEL + c] = (row[c] - m) * inv * sc[c];
}

// ---------------- layernorm (bf16 hi/lo out) ----------------
__global__ void ln_bf16_kernel(const float* __restrict__ in, const float* __restrict__ sc,
                               __nv_bfloat16* __restrict__ oh, __nv_bfloat16* __restrict__ ol) {
    __shared__ float row[DMODEL];
    __shared__ float red[8];
    __shared__ float s_mean, s_inv;
    int r = blockIdx.x, tid = threadIdx.x;
    const float* xr = in + (size_t)r * DMODEL;
    float ls = 0.f;
    for (int c = tid; c < DMODEL; c += 256) { float v = xr[c]; row[c] = v; ls += v; }
    ls = warpSum(ls);
    if ((tid & 31) == 0) red[tid >> 5] = ls;
    __syncthreads();
    if (tid < 8) {
        float t = red[tid];
#pragma unroll
        for (int o = 4; o; o >>= 1) t += __shfl_xor_sync(0xffu, t, o);
        if (tid == 0) s_mean = t / (float)DMODEL;
    }
    __syncthreads();
    float m = s_mean;
    float lv = 0.f;
    for (int c = tid; c < DMODEL; c += 256) { float d = row[c] - m; lv += d * d; }
    lv = warpSum(lv);
    if ((tid & 31) == 0) red[tid >> 5] = lv;
    __syncthreads();
    if (tid < 8) {
        float t = red[tid];
#pragma unroll
        for (int o = 4; o; o >>= 1) t += __shfl_xor_sync(0xffu, t, o);
        if (tid == 0) s_inv = rsqrtf(t / (float)DMODEL + EPSF);
    }
    __syncthreads();
    float inv = s_inv;
    for (int c = tid; c < DMODEL; c += 256) {
        float v = (row[c] - m) * inv * sc[c];
        __nv_bfloat16 h, lo; split_bf16(v, h, lo);
        oh[(size_t)r * DMODEL + c] = h;
        ol[(size_t)r * DMODEL + c] = lo;
    }
}

// ================= bf16-split pipelined tensor-core GEMM =====================
// C[M,N] = A[M,K] @ B^T[N,K]^T with A,B given as bf16 hi/lo pairs.
// Exact-ish: acc = Ah*Bh + Al*Bh + Ah*Bl  (fp32 accumulate)
// flags: 0 = store fp32 C; 1 = C += ; 2 = gelu -> write bf16 hi/lo (Chi/Clo)
#define MMA_BF16(d, a, b)                                                       \
    asm volatile(                                                               \
        "mma.sync.aligned.m16n8k16.row.col.f32.bf16.bf16.f32 "                  \
        "{%0,%1,%2,%3},{%4,%5,%6,%7},{%8,%9},{%0,%1,%2,%3};"                    \
        : "+f"((d)[0]), "+f"((d)[1]), "+f"((d)[2]), "+f"((d)[3])                \
        : "r"((a)[0]), "r"((a)[1]), "r"((a)[2]), "r"((a)[3]),                   \
          "r"((b)[0]), "r"((b)[1]))

#define CP16(dst, src)                                                          \
    asm volatile("cp.async.cg.shared.global [%0], [%1], 16;" ::                 \
                 "r"(dst), "l"(src) : "memory")

// smem row layout: 8 chunks of 16B per 128-row tile row; chunks 0-3 = hi(k0..31),
// 4-7 = lo(k0..31); physical chunk = logical ^ (row & 7)  -> conflict-free frags.
template<int BN>
__device__ __forceinline__ void load_stage_fn(uint32_t base, int tid,
        const __nv_bfloat16* __restrict__ Ah, const __nv_bfloat16* __restrict__ Al,
        const __nv_bfloat16* __restrict__ Bh, const __nv_bfloat16* __restrict__ Bl,
        int K, int kt) {
#pragma unroll
    for (int i = 0; i < 4; i++) {                       // A: 128 rows x 8 chunks
        int cid = tid + i * 256;
        int r = cid >> 3, c = cid & 7;
        const __nv_bfloat16* src =
            (c < 4 ? Ah : Al) + (size_t)r * K + kt * 32 + (c & 3) * 8;
        uint32_t dst = base + r * 128 + ((c ^ (r & 7)) << 4);
        CP16(dst, src);
    }
#pragma unroll
    for (int i = 0; i < BN * 8 / 256; i++) {            // B: BN rows x 8 chunks
        int cid = tid + i * 256;
        int r = cid >> 3, c = cid & 7;
        const __nv_bfloat16* src =
            (c < 4 ? Bh : Bl) + (size_t)r * K + kt * 32 + (c & 3) * 8;
        uint32_t dst = base + 128 * 128 + r * 128 + ((c ^ (r & 7)) << 4);
        CP16(dst, src);
    }
    asm volatile("cp.async.commit_group;" ::: "memory");
}

template<int BN>
__global__ void __launch_bounds__(256, 2) bf16_gemm_kernel(
        const __nv_bfloat16* __restrict__ Ah, const __nv_bfloat16* __restrict__ Al,
        const __nv_bfloat16* __restrict__ Bh, const __nv_bfloat16* __restrict__ Bl,
        float* __restrict__ C, __nv_bfloat16* __restrict__ Chi,
        __nv_bfloat16* __restrict__ Clo,
        int M, int N, int K, int flags) {
    extern __shared__ __align__(128) char smem[];
    constexpr int ASTAGE = 128 * 128;
    constexpr int BSTAGE = BN * 128;
    constexpr int STAGE  = ASTAGE + BSTAGE;
    uint32_t smBase = (uint32_t)__cvta_generic_to_shared(smem);

    const int tid  = threadIdx.x;
    const int lane = tid & 31;
    const int gid  = lane >> 2;
    const int tig  = lane & 3;
    const int warp = tid >> 5;
    constexpr int WM = (BN == 128) ? 2 : 4;
    constexpr int WN = 8 / WM;
    constexpr int MT = (128 / WM) / 16;                 // 4 or 2
    constexpr int NT = (BN / WN) / 8;                   // 4
    const int wm = warp % WM, wn = warp / WM;
    const int mBase = wm * (128 / WM);
    const int nBase = wn * (BN / WN);
    const int blockRow = blockIdx.y * 128;
    const int blockCol = blockIdx.x * BN;

    const __nv_bfloat16* Ah0 = Ah + (size_t)blockRow * K;
    const __nv_bfloat16* Al0 = Al + (size_t)blockRow * K;
    const __nv_bfloat16* Bh0 = Bh + (size_t)blockCol * K;
    const __nv_bfloat16* Bl0 = Bl + (size_t)blockCol * K;

    float acc[MT][NT][4];
#pragma unroll
    for (int i = 0; i < MT; i++)
#pragma unroll
        for (int j = 0; j < NT; j++)
#pragma unroll
            for (int q = 0; q < 4; q++) acc[i][j][q] = 0.f;

    const int KT = K / 32;
    load_stage_fn<BN>(smBase + 0 * STAGE, tid, Ah0, Al0, Bh0, Bl0, K, 0);
    load_stage_fn<BN>(smBase + 1 * STAGE, tid, Ah0, Al0, Bh0, Bl0, K, 1);

    for (int kt = 0; kt < KT; kt++) {
        asm volatile("cp.async.wait_group 1;" ::: "memory");
        __syncthreads();
        if (kt + 2 < KT)
            load_stage_fn<BN>(smBase + ((kt + 2) % 3) * STAGE, tid,
                              Ah0, Al0, Bh0, Bl0, K, kt + 2);
        else
            asm volatile("cp.async.commit_group;" ::: "memory");

        const char* As = smem + (kt % 3) * STAGE;
        const char* Bs = As + ASTAGE;
#pragma unroll
        for (int s = 0; s < 2; s++) {
            const int ck = 2 * s;                       // hi chunks ck, ck+1
            uint32_t ah[MT][4], al[MT][4];
#pragma unroll
            for (int mt = 0; mt < MT; mt++) {
                int r1 = mBase + mt * 16 + gid;
                int r2 = r1 + 8;
                const char* p1 = As + r1 * 128 + (tig << 2);
                const char* p2 = As + r2 * 128 + (tig << 2);
                int x1 = (r1 & 7) << 4, x2 = (r2 & 7) << 4;
                ah[mt][0] = *(const uint32_t*)(p1 + (((ck    ) << 4) ^ x1));
                ah[mt][1] = *(const uint32_t*)(p2 + (((ck    ) << 4) ^ x2));
                ah[mt][2] = *(const uint32_t*)(p1 + (((ck + 1) << 4) ^ x1));
                ah[mt][3] = *(const uint32_t*)(p2 + (((ck + 1) << 4) ^ x2));
                al[mt][0] = *(const uint32_t*)(p1 + (((ck + 4) << 4) ^ x1));
                al[mt][1] = *(const uint32_t*)(p2 + (((ck + 4) << 4) ^ x2));
                al[mt][2] = *(const uint32_t*)(p1 + (((ck + 5) << 4) ^ x1));
                al[mt][3] = *(const uint32_t*)(p2 + (((ck + 5) << 4) ^ x2));
            }
#pragma unroll
            for (int nt = 0; nt < NT; nt++) {
                int rn = nBase + nt * 8 + gid;
                const char* pb = Bs + rn * 128 + (tig << 2);
                int xb = (rn & 7) << 4;
                uint32_t bh[2], bl[2];
                bh[0] = *(const uint32_t*)(pb + (((ck    ) << 4) ^ xb));
                bh[1] = *(const uint32_t*)(pb + (((ck + 1) << 4) ^ xb));
                bl[0] = *(const uint32_t*)(pb + (((ck + 4) << 4) ^ xb));
                bl[1] = *(const uint32_t*)(pb + (((ck + 5) << 4) ^ xb));
#pragma unroll
                for (int mt = 0; mt < MT; mt++) {
                    MMA_BF16(acc[mt][nt], ah[mt], bh);
                    MMA_BF16(acc[mt][nt], al[mt], bh);
                    MMA_BF16(acc[mt][nt], ah[mt], bl);
                }
            }
        }
        __syncthreads();
    }

    // epilogue
#pragma unroll
    for (int mt = 0; mt < MT; mt++) {
#pragma unroll
        for (int nt = 0; nt < NT; nt++) {
            int col = blockCol + nBase + nt * 8 + tig * 2;
            float* a = acc[mt][nt];
#pragma unroll
            for (int hh = 0; hh < 2; hh++) {
                int row = blockRow + mBase + mt * 16 + gid + hh * 8;
                size_t o = (size_t)row * N + col;
                float v0 = a[hh * 2 + 0], v1 = a[hh * 2 + 1];
                if (flags == 2) {
                    float gg0 = gelu_tanh(v0), gg1 = gelu_tanh(v1);
                    __nv_bfloat16 h0, l0, h1, l1;
                    split_bf16(gg0, h0, l0); split_bf16(gg1, h1, l1);
                    Chi[o] = h0; Clo[o] = l0; Chi[o + 1] = h1; Clo[o + 1] = l1;
                } else if (flags == 1) {
                    C[o] += v0; C[o + 1] += v1;
                } else {
                    C[o] = v0; C[o + 1] = v1;
                }
            }
        }
    }
}

static void launch_bf16(const __nv_bfloat16* Ah, const __nv_bfloat16* Al,
                        const __nv_bfloat16* Bh, const __nv_bfloat16* Bl,
                        float* C, __nv_bfloat16* Chi, __nv_bfloat16* Clo,
                        int M, int N, int K, int flags) {
    if (N % 128 == 0 && N >= 2048) {
        constexpr int SMB = 3 * (128 + 128) * 128;
        cudaFuncSetAttribute(bf16_gemm_kernel<128>,
                             cudaFuncAttributeMaxDynamicSharedMemorySize, SMB);
        dim3 grid(N / 128, M / 128);
        bf16_gemm_kernel<128><<<grid, 256, SMB>>>(Ah, Al, Bh, Bl, C, Chi, Clo,
                                                  M, N, K, flags);
    } else {
        constexpr int SMB = 3 * (128 + 64) * 128;
        cudaFuncSetAttribute(bf16_gemm_kernel<64>,
                             cudaFuncAttributeMaxDynamicSharedMemorySize, SMB);
        dim3 grid(N / 64, M / 128);
        bf16_gemm_kernel<64><<<grid, 256, SMB>>>(Ah, Al, Bh, Bl, C, Chi, Clo,
                                                 M, N, K, flags);
    }
}

// ---------------- SIMT fp32 GEMM (embed + Wout only) ----------------
#define BM 64
#define BNS 64
#define BKK 16
__global__ void gemm_kernel(const float* __restrict__ A, const float* __restrict__ B,
                            const float* __restrict__ bias, float* __restrict__ C,
                            int M, int N, int K,
                            int lda, int aRowStart, int aRowStep,
                            int ldb, int bColStart, int bColStep,
                            int ldc, int flags) {
    __shared__ float As[BKK][BM + 4];
    __shared__ float Bs[BKK][BNS + 4];
    int tid = threadIdx.y * 16 + threadIdx.x;
    int rowBase = blockIdx.y * BM;
    int colBase = blockIdx.x * BNS;
    int r0 = threadIdx.y * 4, c0 = threadIdx.x * 4;
    float acc[4][4] = {};
    int aRow = tid >> 2;
    int aK   = (tid & 3) * 4;
    int bRow = tid >> 4;
    int bCol = (tid & 15) * 4;

    for (int kk = 0; kk < K; kk += BKK) {
        {
            int gr = rowBase + aRow;
            float4 v = make_float4(0.f, 0.f, 0.f, 0.f);
            if (gr < M) {
                const float* src = A + (size_t)(aRowStart + gr * aRowStep) * lda + kk + aK;
                v = *(const float4*)src;
            }
            As[aK + 0][aRow] = v.x; As[aK + 1][aRow] = v.y;
            As[aK + 2][aRow] = v.z; As[aK + 3][aRow] = v.w;
        }
        {
            int gc = colBase + bCol;
            if (bColStep == 1) {
                float4 v = make_float4(0.f, 0.f, 0.f, 0.f);
                if (gc < N) {
                    const float* src = B + (size_t)(kk + bRow) * ldb + bColStart + gc;
                    v = *(const float4*)src;
                }
                Bs[bRow][bCol + 0] = v.x; Bs[bRow][bCol + 1] = v.y;
                Bs[bRow][bCol + 2] = v.z; Bs[bRow][bCol + 3] = v.w;
            } else {
#pragma unroll
                for (int j = 0; j < 4; j++) {
                    int c = gc + j;
                    Bs[bRow][bCol + j] = (c < N)
                        ? B[(size_t)(kk + bRow) * ldb + bColStart + c * bColStep] : 0.f;
                }
            }
        }
        __syncthreads();
#pragma unroll
        for (int k = 0; k < BKK; k++) {
            float a[4], bb[4];
#pragma unroll
            for (int i = 0; i < 4; i++) a[i] = As[k][r0 + i];
#pragma unroll
            for (int j = 0; j < 4; j++) bb[j] = Bs[k][c0 + j];
#pragma unroll
            for (int i = 0; i < 4; i++)
#pragma unroll
                for (int j = 0; j < 4; j++) acc[i][j] += a[i] * bb[j];
        }
        __syncthreads();
    }
#pragma unroll
    for (int i = 0; i < 4; i++) {
        int r = rowBase + r0 + i;
        if (r >= M) continue;
#pragma unroll
        for (int j = 0; j < 4; j++) {
            int c = colBase + c0 + j;
            if (c >= N) continue;
            float v = acc[i][j];
            if (flags & 4) v += bias[c];
            size_t o = (size_t)r * ldc + c;
            if (flags & 1) C[o] += v; else C[o] = v;
        }
    }
}

static void launch_gemm(const float* A, const float* B, const float* bias, float* C,
                        int M, int N, int K,
                        int lda, int ars, int arstep,
                        int ldb, int bcs, int bcstep,
                        int ldc, int flags) {
    dim3 grid((N + BNS - 1) / BNS, (M + BM - 1) / BM), block(16, 16);
    gemm_kernel<<<grid, block>>>(A, B, bias, C, M, N, K, lda, ars, arstep,
                                 ldb, bcs, bcstep, ldc, flags);
}

// ---------------- KV cache append ----------------
__global__ void copy_kv_kernel(const float* __restrict__ qkv, float* __restrict__ Kc,
                               float* __restrict__ Vc, int N, int off) {
    int t = blockIdx.x; int b = t / N, n = t % N;
    size_t dst = ((size_t)b * CMAX + off + n) * DMODEL;
    size_t src = (size_t)t * 3 * DMODEL;
    for (int c = threadIdx.x; c < DMODEL; c += blockDim.x) {
        Kc[dst + c] = qkv[src + DMODEL + c];
        Vc[dst + c] = qkv[src + 2 * DMODEL + c];
    }
}

// ---------------- attention (bf16 hi/lo out) ----------------
__global__ void attn_kernel(const float* __restrict__ qkv, const float* __restrict__ Kc,
                            const float* __restrict__ Vc,
                            __nv_bfloat16* __restrict__ outh,
                            __nv_bfloat16* __restrict__ outl,
                            int N, int C, int off) {
    int bh = blockIdx.x; int b = bh / NH, h = bh % NH;
    int n = threadIdx.y, lane = threadIdx.x;
    int t = b * N + n;
    const float* q = qkv + (size_t)t * 3 * DMODEL + h * HDIM;
    int lim = n + off;
    float s = -1e30f;
    if (lane < C && lane <= lim) {
        const float* kr = Kc + ((size_t)b * CMAX + lane) * DMODEL + h * HDIM;
        float d = 0.f;
#pragma unroll
        for (int i = 0; i < HDIM; i++) d += q[i] * kr[i];
        s = d * 0.125f;
    }
    float mx = s;
#pragma unroll
    for (int o = 16; o; o >>= 1) mx = fmaxf(mx, __shfl_xor_sync(0xffffffffu, mx, o));
    float p = (lane < C && lane <= lim) ? expf(s - mx) : 0.f;
    float sum = warpSum(p);
    float a0 = 0.f, a1 = 0.f;
    int mmax = min(lim, C - 1);
    for (int m = 0; m <= mmax; m++) {
        float pm = __shfl_sync(0xffffffffu, p, m);
        const float* vr = Vc + ((size_t)b * CMAX + m) * DMODEL + h * HDIM;
        a0 += pm * vr[lane];
        a1 += pm * vr[lane + 32];
    }
    float inv = 1.f / sum;
    float v0 = a0 * inv, v1 = a1 * inv;
    size_t i0 = (size_t)t * DMODEL + h * HDIM + lane;
    __nv_bfloat16 h0, l0, h1, l1;
    split_bf16(v0, h0, l0); split_bf16(v1, h1, l1);
    outh[i0] = h0;      outl[i0] = l0;
    outh[i0 + 32] = h1; outl[i0 + 32] = l1;
}

// ---------------- epilogue kernels ----------------
__global__ void revin_last_kernel() {
    int b = blockIdx.x, o = threadIdx.x;
    g_last[b * 128 + o] = g_no1[b * 128 + o] * (g_ctxsg[b * NPATCH + 15] + EPSF)
                        + g_ctxmu[b * NPATCH + 15];
}

__global__ void assemble_kernel(float* __restrict__ out) {
    int idx = blockIdx.x * blockDim.x + threadIdx.x;
    int b = idx / 256, t = idx % 256;
    float m;
    if (t < 128) {
        m = 0.5f * (g_last[b * 128 + t] - g_last[(b + 32) * 128 + t]);
    } else {
        int o = t - 128;
        float va = g_no2[b * 128 + o]        * (g_nsg[b * 4 + 3] + EPSF)        + g_nmu[b * 4 + 3];
        float vb = g_no2[(b + 32) * 128 + o] * (g_nsg[(b + 32) * 4 + 3] + EPSF) + g_nmu[(b + 32) * 4 + 3];
        m = 0.5f * (va - vb);
    }
    if (g_ispos[b]) m = fmaxf(m, 0.f);
    out[idx] = m;
}

// ---------------- pointers bundle ----------------
struct DevPtrs {
    float *normed, *anorm, *hdd, *xn, *qkv, *Kc, *Vc, *no1, *no2;
    __nv_bfloat16 *xnh, *xnl, *atth, *attl, *h1h, *h1l;
    __nv_bfloat16 *qkvh, *qkvl, *woh, *wol, *w1h, *w1l, *w2h, *w2l;
};

// ---------------- full transformer forward ----------------
static void model_fwd_host(const DevPtrs& P, int T, int N, int C, int off,
                           const float* in_tok,
                           const float* W_in, const float* b_in, const float* ln1,
                           const float* ln2, const float* lnf, const float* Wout,
                           float* nosel, int selStart, int selStep) {
    launch_gemm(in_tok, W_in, b_in, P.hdd, T, DMODEL, PATCH,
                PATCH, 0, 1, DMODEL, 0, 1, DMODEL, 4);
    for (int l = 0; l < NLAYER; l++) {
        ln_bf16_kernel<<<T, 256>>>(P.hdd, ln1 + (size_t)l * DMODEL, P.xnh, P.xnl);
        launch_bf16(P.xnh, P.xnl,
                    P.qkvh + (size_t)l * 3072 * 1024, P.qkvl + (size_t)l * 3072 * 1024,
                    P.qkv, nullptr, nullptr, T, 3 * DMODEL, DMODEL, 0);
        float* Kl = P.Kc + (size_t)l * NB * CMAX * DMODEL;
        float* Vl = P.Vc + (size_t)l * NB * CMAX * DMODEL;
        copy_kv_kernel<<<T, 256>>>(P.qkv, Kl, Vl, N, off);
        attn_kernel<<<NB * NH, dim3(32, N)>>>(P.qkv, Kl, Vl, P.atth, P.attl, N, C, off);
        launch_bf16(P.atth, P.attl,
                    P.woh + (size_t)l * 1024 * 1024, P.wol + (size_t)l * 1024 * 1024,
                    P.hdd, nullptr, nullptr, T, DMODEL, DMODEL, 1);
        ln_bf16_kernel<<<T, 256>>>(P.hdd, ln2 + (size_t)l * DMODEL, P.xnh, P.xnl);
        launch_bf16(P.xnh, P.xnl,
                    P.w1h + (size_t)l * 4096 * 1024, P.w1l + (size_t)l * 4096 * 1024,
                    nullptr, P.h1h, P.h1l, T, NDFF, DMODEL, 2);
        launch_bf16(P.h1h, P.h1l,
                    P.w2h + (size_t)l * 1024 * 4096, P.w2l + (size_t)l * 1024 * 4096,
                    P.hdd, nullptr, nullptr, T, DMODEL, NDFF, 1);
    }
    ln_kernel<<<T, 256>>>(P.hdd, lnf, P.xn);
    launch_gemm(P.xn, Wout, nullptr, nosel, NB, 128, DMODEL,
                DMODEL, selStart, selStep, 1280, 5, 10, 128, 0);
}

// ---------------- entry ----------------
extern "C" void kernel_launch(void* const* d_in, const int* in_sizes, int n_in,
                              void* d_out, int out_size) {
    const float* x     = (const float*)d_in[0];
    const float* W_in  = (const float*)d_in[1];
    const float* b_in  = (const float*)d_in[2];
    const float* ln1_s = (const float*)d_in[3];
    const float* Wqkv  = (const float*)d_in[4];
    const float* Wo    = (const float*)d_in[5];
    const float* ln2_s = (const float*)d_in[6];
    const float* W1    = (const float*)d_in[7];
    const float* W2    = (const float*)d_in[8];
    const float* lnf_s = (const float*)d_in[9];
    const float* Wout  = (const float*)d_in[10];
    // d_in[11] = Wqs: provably unused for the median (channel-5) output

    DevPtrs P;
    cudaGetSymbolAddress((void**)&P.normed, g_normed);
    cudaGetSymbolAddress((void**)&P.anorm,  g_anorm);
    cudaGetSymbolAddress((void**)&P.hdd,    g_hdd);
    cudaGetSymbolAddress((void**)&P.xn,     g_xn);
    cudaGetSymbolAddress((void**)&P.qkv,    g_qkv);
    cudaGetSymbolAddress((void**)&P.Kc,     g_Kc);
    cudaGetSymbolAddress((void**)&P.Vc,     g_Vc);
    cudaGetSymbolAddress((void**)&P.no1,    g_no1);
    cudaGetSymbolAddress((void**)&P.no2,    g_no2);
    cudaGetSymbolAddress((void**)&P.xnh,    g_xnh);
    cudaGetSymbolAddress((void**)&P.xnl,    g_xnl);
    cudaGetSymbolAddress((void**)&P.atth,   g_atth);
    cudaGetSymbolAddress((void**)&P.attl,   g_attl);
    cudaGetSymbolAddress((void**)&P.h1h,    g_h1h);
    cudaGetSymbolAddress((void**)&P.h1l,    g_h1l);
    cudaGetSymbolAddress((void**)&P.qkvh,   g_Wqkvh);
    cudaGetSymbolAddress((void**)&P.qkvl,   g_Wqkvl);
    cudaGetSymbolAddress((void**)&P.woh,    g_Woh);
    cudaGetSymbolAddress((void**)&P.wol,    g_Wol);
    cudaGetSymbolAddress((void**)&P.w1h,    g_W1h);
    cudaGetSymbolAddress((void**)&P.w1l,    g_W1l);
    cudaGetSymbolAddress((void**)&P.w2h,    g_W2h);
    cudaGetSymbolAddress((void**)&P.w2l,    g_W2l);

    // Stage 0: weight transpose + bf16 split (once per launch)
    convT_kernel<<<dim3(3072 / 32, 1024 / 32, NLAYER), dim3(32, 8)>>>(Wqkv, P.qkvh, P.qkvl, 1024, 3072);
    convT_kernel<<<dim3(1024 / 32, 1024 / 32, NLAYER), dim3(32, 8)>>>(Wo,   P.woh,  P.wol,  1024, 1024);
    convT_kernel<<<dim3(4096 / 32, 1024 / 32, NLAYER), dim3(32, 8)>>>(W1,   P.w1h,  P.w1l,  1024, 4096);
    convT_kernel<<<dim3(1024 / 32, 4096 / 32, NLAYER), dim3(32, 8)>>>(W2,   P.w2h,  P.w2l,  4096, 1024);

    // Stage A: running stats + normalization for x and -x (batch 64)
    stats_kernel<<<NB, 32>>>(x);

    // Stage B: prefill (C=16, offset 0)
    model_fwd_host(P, T1, NPATCH, 16, 0, P.normed,
                   W_in, b_in, ln1_s, ln2_s, lnf_s, Wout,
                   P.no1, /*selStart=*/15, /*selStep=*/16);
    revin_last_kernel<<<NB, 128>>>();

    // Stage C: AR stats + one autoregressive step (C=20, offset 16)
    ar_stats_kernel<<<NB, 32>>>();
    model_fwd_host(P, T2, 4, 20, 16, P.anorm,
                   W_in, b_in, ln1_s, ln2_s, lnf_s, Wout,
                   P.no2, /*selStart=*/3, /*selStep=*/4);

    // Stage D: combine x / -x, clamp, write [32,256]
    assemble_kernel<<<32, 256>>>((float*)d_out);
}

// round 4
// speedup vs baseline: 3.8371x; 1.2731x over previous
#include <cuda_runtime.h>
#include <cuda_bf16.h>
#include <math.h>
#include <stdint.h>

// ---------------- constants ----------------
#define NB      64
#define NPATCH  16
#define PATCH   32
#define DMODEL  1024
#define NH      16
#define HDIM    64
#define NDFF    4096
#define NLAYER  8
#define CMAX    20
#define T1      1024
#define T2      256
#define EPSF    1e-6f

// ---------------- device scratch ----------------
__device__ float g_normed[T1 * PATCH];
__device__ float g_anorm [T2 * PATCH];
__device__ float g_ctxmu [NB * NPATCH];
__device__ float g_ctxsg [NB * NPATCH];
__device__ float g_nmu   [NB * 4];
__device__ float g_nsg   [NB * 4];
__device__ int   g_ispos [32];
__device__ float g_hdd [T1 * DMODEL];
__device__ float g_xn  [T1 * DMODEL];
__device__ float g_qkv [T1 * 3 * DMODEL];
__device__ float g_Kc  [NLAYER * NB * CMAX * DMODEL];
__device__ float g_Vc  [NLAYER * NB * CMAX * DMODEL];
__device__ float g_no1 [NB * 128];
__device__ float g_no2 [NB * 128];
__device__ float g_last[NB * 128];
__device__ float g_Wsel[1024 * 128];

// bf16 hi/lo activation buffers
__device__ __nv_bfloat16 g_xnh [T1 * DMODEL], g_xnl [T1 * DMODEL];
__device__ __nv_bfloat16 g_atth[T1 * DMODEL], g_attl[T1 * DMODEL];
__device__ __nv_bfloat16 g_h1h [T1 * NDFF],   g_h1l [T1 * NDFF];

// transposed bf16 hi/lo weights: [L][N][K]
__device__ __nv_bfloat16 g_Wqkvh[(size_t)NLAYER * 3072 * 1024];
__device__ __nv_bfloat16 g_Wqkvl[(size_t)NLAYER * 3072 * 1024];
__device__ __nv_bfloat16 g_Woh [(size_t)NLAYER * 1024 * 1024];
__device__ __nv_bfloat16 g_Wol [(size_t)NLAYER * 1024 * 1024];
__device__ __nv_bfloat16 g_W1h [(size_t)NLAYER * 4096 * 1024];
__device__ __nv_bfloat16 g_W1l [(size_t)NLAYER * 4096 * 1024];
__device__ __nv_bfloat16 g_W2h [(size_t)NLAYER * 1024 * 4096];
__device__ __nv_bfloat16 g_W2l [(size_t)NLAYER * 1024 * 4096];

// ---------------- helpers ----------------
__device__ __forceinline__ float warpSum(float v) {
#pragma unroll
    for (int o = 16; o; o >>= 1) v += __shfl_xor_sync(0xffffffffu, v, o);
    return v;
}

__device__ __forceinline__ float gelu_tanh(float x) {
    float x3 = x * x * x;
    return 0.5f * x * (1.0f + tanhf(0.7978845608028654f * (x + 0.044715f * x3)));
}

__device__ __forceinline__ void split_bf16(float v, __nv_bfloat16& h, __nv_bfloat16& l) {
    h = __float2bfloat16(v);
    l = __float2bfloat16(v - __bfloat162float(h));
}

// ---------------- weight transpose + bf16 split ----------------
__global__ void convT_kernel(const float* __restrict__ W,
                             __nv_bfloat16* __restrict__ Th,
                             __nv_bfloat16* __restrict__ Tl, int K, int N) {
    __shared__ float t[32][33];
    int l = blockIdx.z;
    const float* Wl = W + (size_t)l * K * N;
    __nv_bfloat16* Thl = Th + (size_t)l * K * N;
    __nv_bfloat16* Tll = Tl + (size_t)l * K * N;
    int n0 = blockIdx.x * 32, k0 = blockIdx.y * 32;
#pragma unroll
    for (int i = 0; i < 4; i++)
        t[threadIdx.y + 8 * i][threadIdx.x] =
            Wl[(size_t)(k0 + threadIdx.y + 8 * i) * N + n0 + threadIdx.x];
    __syncthreads();
#pragma unroll
    for (int i = 0; i < 4; i++) {
        int n = threadIdx.y + 8 * i;
        float v = t[threadIdx.x][n];
        __nv_bfloat16 h, lo; split_bf16(v, h, lo);
        size_t o = (size_t)(n0 + n) * K + k0 + threadIdx.x;
        Thl[o] = h; Tll[o] = lo;
    }
}

// ---------------- Wout channel-5 column extraction: [K][128] ----------------
__global__ void wsel_kernel(const float* __restrict__ Wout) {
    int i = blockIdx.x * blockDim.x + threadIdx.x;   // 131072 total
    int k = i >> 7, j = i & 127;
    g_Wsel[i] = Wout[k * 1280 + 5 + 10 * j];
}

// ---------------- Wout GEMM: out[b][j] = xn[row_b] . Wsel[:,j] -------------
__global__ void wout_kernel(const float* __restrict__ xn, float* __restrict__ outv,
                            int selStart, int selStep) {
    __shared__ float sx[8][1024];
    int j = threadIdx.x;                              // 0..127
    int b0 = blockIdx.x * 8;
#pragma unroll
    for (int i = 0; i < 8; i++) {
        int row = selStart + (b0 + i) * selStep;
        for (int c = j; c < 1024; c += 128) sx[i][c] = xn[(size_t)row * 1024 + c];
    }
    __syncthreads();
    float acc[8] = {};
    for (int k = 0; k < 1024; k++) {
        float w = g_Wsel[k * 128 + j];
#pragma unroll
        for (int i = 0; i < 8; i++) acc[i] += sx[i][k] * w;
    }
#pragma unroll
    for (int i = 0; i < 8; i++) outv[(b0 + i) * 128 + j] = acc[i];
}

// ---------------- running stats ----------------
__global__ void stats_kernel(const float* __restrict__ x) {
    int b = blockIdx.x, lane = threadIdx.x;
    const float* xb = x + (size_t)(b & 31) * 512;
    float sign = (b < 32) ? 1.f : -1.f;
    if (b < 32) {
        bool ok = true;
        for (int i = lane; i < 512; i += 32) ok = ok && (xb[i] >= 0.f);
        unsigned bal = __ballot_sync(0xffffffffu, ok);
        if (lane == 0) g_ispos[b] = (bal == 0xffffffffu) ? 1 : 0;
    }
    float n = 0.f, mu = 0.f, sg = 0.f;
    for (int p = 0; p < NPATCH; p++) {
        float v = sign * xb[p * PATCH + lane];
        float s = warpSum(v);
        float nn = n + 32.f;
        float nmu = (n * mu + s) / nn;
        float m2 = n * sg * sg + warpSum((v - mu) * (v - nmu));
        float nsg = sqrtf(fmaxf(m2 / nn, 1e-12f));
        n = nn; mu = nmu; sg = nsg;
        if (lane == 0) { g_ctxmu[b * NPATCH + p] = mu; g_ctxsg[b * NPATCH + p] = sg; }
        g_normed[(b * NPATCH + p) * PATCH + lane] = (v - mu) / (sg + EPSF);
    }
}

__global__ void ar_stats_kernel() {
    int b = blockIdx.x, lane = threadIdx.x;
    float n = 512.f, mu = g_ctxmu[b * NPATCH + 15], sg = g_ctxsg[b * NPATCH + 15];
    for (int p = 0; p < 4; p++) {
        float v = g_last[b * 128 + p * PATCH + lane];
        float s = warpSum(v);
        float nn = n + 32.f;
        float nmu = (n * mu + s) / nn;
        float m2 = n * sg * sg + warpSum((v - mu) * (v - nmu));
        float ns = sqrtf(fmaxf(m2 / nn, 1e-12f));
        n = nn; mu = nmu; sg = ns;
        if (lane == 0) { g_nmu[b * 4 + p] = mu; g_nsg[b * 4 + p] = ns; }
        g_anorm[(b * 4 + p) * PATCH + lane] = (v - mu) / (sg + EPSF);
    }
}

// ---------------- layernorms ----------------
__global__ void ln_kernel(const float* __restrict__ in, const float* __restrict__ sc,
                          float* __restrict__ out) {
    __shared__ float row[DMODEL];
    __shared__ float red[8];
    __shared__ float s_mean, s_inv;
    int r = blockIdx.x, tid = threadIdx.x;
    const float* xr = in + (size_t)r * DMODEL;
    float ls = 0.f;
    for (int c = tid; c < DMODEL; c += 256) { float v = xr[c]; row[c] = v; ls += v; }
    ls = warpSum(ls);
    if ((tid & 31) == 0) red[tid >> 5] = ls;
    __syncthreads();
    if (tid < 8) {
        float t = red[tid];
#pragma unroll
        for (int o = 4; o; o >>= 1) t += __shfl_xor_sync(0xffu, t, o);
        if (tid == 0) s_mean = t / (float)DMODEL;
    }
    __syncthreads();
    float m = s_mean;
    float lv = 0.f;
    for (int c = tid; c < DMODEL; c += 256) { float d = row[c] - m; lv += d * d; }
    lv = warpSum(lv);
    if ((tid & 31) == 0) red[tid >> 5] = lv;
    __syncthreads();
    if (tid < 8) {
        float t = red[tid];
#pragma unroll
        for (int o = 4; o; o >>= 1) t += __shfl_xor_sync(0xffu, t, o);
        if (tid == 0) s_inv = rsqrtf(t / (float)DMODEL + EPSF);
    }
    __syncthreads();
    float inv = s_inv;
    for (int c = tid; c < DMODEL; c += 256)
        out[(size_t)r * DMODEL + c] = (row[c] - m) * inv * sc[c];
}

__global__ void ln_bf16_kernel(const float* __restrict__ in, const float* __restrict__ sc,
                               __nv_bfloat16* __restrict__ oh, __nv_bfloat16* __restrict__ ol) {
    __shared__ float row[DMODEL];
    __shared__ float red[8];
    __shared__ float s_mean, s_inv;
    int r = blockIdx.x, tid = threadIdx.x;
    const float* xr = in + (size_t)r * DMODEL;
    float ls = 0.f;
    for (int c = tid; c < DMODEL; c += 256) { float v = xr[c]; row[c] = v; ls += v; }
    ls = warpSum(ls);
    if ((tid & 31) == 0) red[tid >> 5] = ls;
    __syncthreads();
    if (tid < 8) {
        float t = red[tid];
#pragma unroll
        for (int o = 4; o; o >>= 1) t += __shfl_xor_sync(0xffu, t, o);
        if (tid == 0) s_mean = t / (float)DMODEL;
    }
    __syncthreads();
    float m = s_mean;
    float lv = 0.f;
    for (int c = tid; c < DMODEL; c += 256) { float d = row[c] - m; lv += d * d; }
    lv = warpSum(lv);
    if ((tid & 31) == 0) red[tid >> 5] = lv;
    __syncthreads();
    if (tid < 8) {
        float t = red[tid];
#pragma unroll
        for (int o = 4; o; o >>= 1) t += __shfl_xor_sync(0xffu, t, o);
        if (tid == 0) s_inv = rsqrtf(t / (float)DMODEL + EPSF);
    }
    __syncthreads();
    float inv = s_inv;
    for (int c = tid; c < DMODEL; c += 256) {
        float v = (row[c] - m) * inv * sc[c];
        __nv_bfloat16 h, lo; split_bf16(v, h, lo);
        oh[(size_t)r * DMODEL + c] = h;
        ol[(size_t)r * DMODEL + c] = lo;
    }
}

// ================= bf16-split tensor-core GEMM, ldmatrix fragments ==========
#define MMA_BF16(d, a, b)                                                       \
    asm volatile(                                                               \
        "mma.sync.aligned.m16n8k16.row.col.f32.bf16.bf16.f32 "                  \
        "{%0,%1,%2,%3},{%4,%5,%6,%7},{%8,%9},{%0,%1,%2,%3};"                    \
        : "+f"((d)[0]), "+f"((d)[1]), "+f"((d)[2]), "+f"((d)[3])                \
        : "r"((a)[0]), "r"((a)[1]), "r"((a)[2]), "r"((a)[3]),                   \
          "r"((b)[0]), "r"((b)[1]))

#define LDSM4(r0, r1, r2, r3, addr)                                             \
    asm volatile("ldmatrix.sync.aligned.m8n8.x4.shared.b16 {%0,%1,%2,%3},[%4];" \
        : "=r"(r0), "=r"(r1), "=r"(r2), "=r"(r3) : "r"(addr))

#define CP16(dst, src)                                                          \
    asm volatile("cp.async.cg.shared.global [%0], [%1], 16;" ::                 \
                 "r"(dst), "l"(src) : "memory")

// smem row: 8 chunks of 16B; chunks 0-3 = hi(k0..31), 4-7 = lo(k0..31);
// physical chunk = logical ^ (row & 7)
template<int BM, int BN>
__device__ __forceinline__ void load_stage_fn(uint32_t base, int tid,
        const __nv_bfloat16* __restrict__ Ah, const __nv_bfloat16* __restrict__ Al,
        const __nv_bfloat16* __restrict__ Bh, const __nv_bfloat16* __restrict__ Bl,
        int K, int kt) {
#pragma unroll
    for (int i = 0; i < BM * 8 / 256; i++) {
        int cid = tid + i * 256;
        int r = cid >> 3, c = cid & 7;
        const __nv_bfloat16* src =
            (c < 4 ? Ah : Al) + (size_t)r * K + kt * 32 + (c & 3) * 8;
        uint32_t dst = base + r * 128 + ((c ^ (r & 7)) << 4);
        CP16(dst, src);
    }
#pragma unroll
    for (int i = 0; i < BN * 8 / 256; i++) {
        int cid = tid + i * 256;
        int r = cid >> 3, c = cid & 7;
        const __nv_bfloat16* src =
            (c < 4 ? Bh : Bl) + (size_t)r * K + kt * 32 + (c & 3) * 8;
        uint32_t dst = base + BM * 128 + r * 128 + ((c ^ (r & 7)) << 4);
        CP16(dst, src);
    }
    asm volatile("cp.async.commit_group;" ::: "memory");
}

template<int BM, int BN>
__global__ void __launch_bounds__(256, (BM == 128 || BN == 128) ? 2 : 3)
bf16_gemm_kernel(
        const __nv_bfloat16* __restrict__ Ah, const __nv_bfloat16* __restrict__ Al,
        const __nv_bfloat16* __restrict__ Bh, const __nv_bfloat16* __restrict__ Bl,
        float* __restrict__ C, __nv_bfloat16* __restrict__ Chi,
        __nv_bfloat16* __restrict__ Clo,
        int M, int N, int K, int flags) {
    extern __shared__ __align__(128) char smem[];
    constexpr int ASTAGE = BM * 128;
    constexpr int BSTAGE = BN * 128;
    constexpr int STAGE  = ASTAGE + BSTAGE;
    uint32_t smBase = (uint32_t)__cvta_generic_to_shared(smem);

    const int tid  = threadIdx.x;
    const int lane = tid & 31;
    const int gid  = lane >> 2;
    const int tig  = lane & 3;
    const int warp = tid >> 5;
    constexpr int MT = (BM / 2) / 16;                 // 4 (BM=128) or 2 (64)
    constexpr int NT = (BN / 4) / 8;                  // 4 (BN=128) or 2 (64)
    const int wm = warp & 1, wn = warp >> 1;
    const int mBase = wm * (BM / 2);
    const int nBase = wn * (BN / 4);
    const int blockRow = blockIdx.y * BM;
    const int blockCol = blockIdx.x * BN;

    const __nv_bfloat16* Ah0 = Ah + (size_t)blockRow * K;
    const __nv_bfloat16* Al0 = Al + (size_t)blockRow * K;
    const __nv_bfloat16* Bh0 = Bh + (size_t)blockCol * K;
    const __nv_bfloat16* Bl0 = Bl + (size_t)blockCol * K;

    float acc[MT][NT][4];
#pragma unroll
    for (int i = 0; i < MT; i++)
#pragma unroll
        for (int j = 0; j < NT; j++)
#pragma unroll
            for (int q = 0; q < 4; q++) acc[i][j][q] = 0.f;

    const int KT = K / 32;
    load_stage_fn<BM, BN>(smBase + 0 * STAGE, tid, Ah0, Al0, Bh0, Bl0, K, 0);
    load_stage_fn<BM, BN>(smBase + 1 * STAGE, tid, Ah0, Al0, Bh0, Bl0, K, 1);

    // per-lane fragment address components
    const int arow = (lane & 7) + ((lane >> 3) & 1) * 8;   // row offset in m-tile
    const int acsel = lane >> 4;                           // chunk select 0/1
    const int nrow = lane & 7;
    const int bcsel = (lane >> 3) & 1;
    const int ntsel = lane >> 4;

    for (int kt = 0; kt < KT; kt++) {
        asm volatile("cp.async.wait_group 1;" ::: "memory");
        __syncthreads();
        if (kt + 2 < KT)
            load_stage_fn<BM, BN>(smBase + ((kt + 2) % 3) * STAGE, tid,
                                  Ah0, Al0, Bh0, Bl0, K, kt + 2);
        else
            asm volatile("cp.async.commit_group;" ::: "memory");

        uint32_t AsA = smBase + (kt % 3) * STAGE;
        uint32_t BsA = AsA + ASTAGE;
#pragma unroll
        for (int s = 0; s < 2; s++) {
            const int ck = 2 * s;
            uint32_t ah[MT][4], al[MT][4];
#pragma unroll
            for (int mt = 0; mt < MT; mt++) {
                int r = mBase + mt * 16 + arow;
                uint32_t rb = AsA + r * 128;
                int xr = r & 7;
                LDSM4(ah[mt][0], ah[mt][1], ah[mt][2], ah[mt][3],
                      rb + (((ck + acsel) ^ xr) << 4));
                LDSM4(al[mt][0], al[mt][1], al[mt][2], al[mt][3],
                      rb + (((ck + 4 + acsel) ^ xr) << 4));
            }
            uint32_t bh[NT][2], bl[NT][2];
#pragma unroll
            for (int np = 0; np < NT / 2; np++) {
                int nt0 = np * 2;
                int r = nBase + (nt0 + ntsel) * 8 + nrow;
                uint32_t rb = BsA + r * 128;
                int xr = r & 7;
                LDSM4(bh[nt0][0], bh[nt0][1], bh[nt0 + 1][0], bh[nt0 + 1][1],
                      rb + (((ck + bcsel) ^ xr) << 4));
                LDSM4(bl[nt0][0], bl[nt0][1], bl[nt0 + 1][0], bl[nt0 + 1][1],
                      rb + (((ck + 4 + bcsel) ^ xr) << 4));
            }
#pragma unroll
            for (int nt = 0; nt < NT; nt++)
#pragma unroll
                for (int mt = 0; mt < MT; mt++) {
                    MMA_BF16(acc[mt][nt], ah[mt], bh[nt]);
                    MMA_BF16(acc[mt][nt], al[mt], bh[nt]);
                    MMA_BF16(acc[mt][nt], ah[mt], bl[nt]);
                }
        }
        __syncthreads();
    }

    // epilogue
#pragma unroll
    for (int mt = 0; mt < MT; mt++) {
#pragma unroll
        for (int nt = 0; nt < NT; nt++) {
            int col = blockCol + nBase + nt * 8 + tig * 2;
            float* a = acc[mt][nt];
#pragma unroll
            for (int hh = 0; hh < 2; hh++) {
                int row = blockRow + mBase + mt * 16 + gid + hh * 8;
                size_t o = (size_t)row * N + col;
                float v0 = a[hh * 2 + 0], v1 = a[hh * 2 + 1];
                if (flags == 2) {
                    float gg0 = gelu_tanh(v0), gg1 = gelu_tanh(v1);
                    __nv_bfloat16 h0, l0, h1, l1;
                    split_bf16(gg0, h0, l0); split_bf16(gg1, h1, l1);
                    Chi[o] = h0; Clo[o] = l0; Chi[o + 1] = h1; Clo[o + 1] = l1;
                } else if (flags == 1) {
                    C[o] += v0; C[o + 1] += v1;
                } else {
                    C[o] = v0; C[o + 1] = v1;
                }
            }
        }
    }
}

static void launch_bf16(const __nv_bfloat16* Ah, const __nv_bfloat16* Al,
                        const __nv_bfloat16* Bh, const __nv_bfloat16* Bl,
                        float* C, __nv_bfloat16* Chi, __nv_bfloat16* Clo,
                        int M, int N, int K, int flags) {
    if (M >= 1024 && N >= 2048) {
        constexpr int SMB = 3 * (128 + 128) * 128;
        cudaFuncSetAttribute(bf16_gemm_kernel<128, 128>,
                             cudaFuncAttributeMaxDynamicSharedMemorySize, SMB);
        dim3 grid(N / 128, M / 128);
        bf16_gemm_kernel<128, 128><<<grid, 256, SMB>>>(Ah, Al, Bh, Bl, C, Chi, Clo,
                                                       M, N, K, flags);
    } else if (M >= 1024) {
        constexpr int SMB = 3 * (64 + 128) * 128;
        cudaFuncSetAttribute(bf16_gemm_kernel<64, 128>,
                             cudaFuncAttributeMaxDynamicSharedMemorySize, SMB);
        dim3 grid(N / 128, M / 64);
        bf16_gemm_kernel<64, 128><<<grid, 256, SMB>>>(Ah, Al, Bh, Bl, C, Chi, Clo,
                                                      M, N, K, flags);
    } else {
        constexpr int SMB = 3 * (64 + 64) * 128;
        cudaFuncSetAttribute(bf16_gemm_kernel<64, 64>,
                             cudaFuncAttributeMaxDynamicSharedMemorySize, SMB);
        dim3 grid(N / 64, M / 64);
        bf16_gemm_kernel<64, 64><<<grid, 256, SMB>>>(Ah, Al, Bh, Bl, C, Chi, Clo,
                                                     M, N, K, flags);
    }
}

// ---------------- SIMT fp32 GEMM (embed only) ----------------
#define BMs 64
#define BNs 64
#define BKK 16
__global__ void gemm_kernel(const float* __restrict__ A, const float* __restrict__ B,
                            const float* __restrict__ bias, float* __restrict__ C,
                            int M, int N, int K, int lda, int ldb, int ldc) {
    __shared__ float As[BKK][BMs + 4];
    __shared__ float Bs[BKK][BNs + 4];
    int tid = threadIdx.y * 16 + threadIdx.x;
    int rowBase = blockIdx.y * BMs;
    int colBase = blockIdx.x * BNs;
    int r0 = threadIdx.y * 4, c0 = threadIdx.x * 4;
    float acc[4][4] = {};
    int aRow = tid >> 2;
    int aK   = (tid & 3) * 4;
    int bRow = tid >> 4;
    int bCol = (tid & 15) * 4;

    for (int kk = 0; kk < K; kk += BKK) {
        {
            int gr = rowBase + aRow;
            float4 v = make_float4(0.f, 0.f, 0.f, 0.f);
            if (gr < M) v = *(const float4*)(A + (size_t)gr * lda + kk + aK);
            As[aK + 0][aRow] = v.x; As[aK + 1][aRow] = v.y;
            As[aK + 2][aRow] = v.z; As[aK + 3][aRow] = v.w;
        }
        {
            int gc = colBase + bCol;
            float4 v = make_float4(0.f, 0.f, 0.f, 0.f);
            if (gc < N) v = *(const float4*)(B + (size_t)(kk + bRow) * ldb + gc);
            Bs[bRow][bCol + 0] = v.x; Bs[bRow][bCol + 1] = v.y;
            Bs[bRow][bCol + 2] = v.z; Bs[bRow][bCol + 3] = v.w;
        }
        __syncthreads();
#pragma unroll
        for (int k = 0; k < BKK; k++) {
            float a[4], bb[4];
#pragma unroll
            for (int i = 0; i < 4; i++) a[i] = As[k][r0 + i];
#pragma unroll
            for (int j = 0; j < 4; j++) bb[j] = Bs[k][c0 + j];
#pragma unroll
            for (int i = 0; i < 4; i++)
#pragma unroll
                for (int j = 0; j < 4; j++) acc[i][j] += a[i] * bb[j];
        }
        __syncthreads();
    }
#pragma unroll
    for (int i = 0; i < 4; i++) {
        int r = rowBase + r0 + i;
        if (r >= M) continue;
#pragma unroll
        for (int j = 0; j < 4; j++) {
            int c = colBase + c0 + j;
            if (c >= N) continue;
            C[(size_t)r * ldc + c] = acc[i][j] + bias[c];
        }
    }
}

// ---------------- attention with fused KV-cache append ----------------
__global__ void attn_kernel(const float* __restrict__ qkv, float* __restrict__ Kc,
                            float* __restrict__ Vc,
                            __nv_bfloat16* __restrict__ outh,
                            __nv_bfloat16* __restrict__ outl,
                            int N, int C, int off) {
    int bh = blockIdx.x; int b = bh / NH, h = bh % NH;
    int n = threadIdx.y, lane = threadIdx.x;
    int t = b * N + n;
    // append this token's K/V head-slice to the cache
    size_t src = (size_t)t * 3 * DMODEL + h * HDIM;
    size_t dst = ((size_t)b * CMAX + off + n) * DMODEL + h * HDIM;
    Kc[dst + lane]      = qkv[src + DMODEL + lane];
    Kc[dst + lane + 32] = qkv[src + DMODEL + lane + 32];
    Vc[dst + lane]      = qkv[src + 2 * DMODEL + lane];
    Vc[dst + lane + 32] = qkv[src + 2 * DMODEL + lane + 32];
    __syncthreads();

    const float* q = qkv + src;
    int lim = n + off;
    float s = -1e30f;
    if (lane < C && lane <= lim) {
        const float* kr = Kc + ((size_t)b * CMAX + lane) * DMODEL + h * HDIM;
        float d = 0.f;
#pragma unroll
        for (int i = 0; i < HDIM; i++) d += q[i] * kr[i];
        s = d * 0.125f;
    }
    float mx = s;
#pragma unroll
    for (int o = 16; o; o >>= 1) mx = fmaxf(mx, __shfl_xor_sync(0xffffffffu, mx, o));
    float p = (lane < C && lane <= lim) ? expf(s - mx) : 0.f;
    float sum = warpSum(p);
    float a0 = 0.f, a1 = 0.f;
    int mmax = min(lim, C - 1);
    for (int m = 0; m <= mmax; m++) {
        float pm = __shfl_sync(0xffffffffu, p, m);
        const float* vr = Vc + ((size_t)b * CMAX + m) * DMODEL + h * HDIM;
        a0 += pm * vr[lane];
        a1 += pm * vr[lane + 32];
    }
    float inv = 1.f / sum;
    float v0 = a0 * inv, v1 = a1 * inv;
    size_t i0 = (size_t)t * DMODEL + h * HDIM + lane;
    __nv_bfloat16 h0, l0, h1, l1;
    split_bf16(v0, h0, l0); split_bf16(v1, h1, l1);
    outh[i0] = h0;      outl[i0] = l0;
    outh[i0 + 32] = h1; outl[i0 + 32] = l1;
}

// ---------------- epilogue kernels ----------------
__global__ void revin_last_kernel() {
    int b = blockIdx.x, o = threadIdx.x;
    g_last[b * 128 + o] = g_no1[b * 128 + o] * (g_ctxsg[b * NPATCH + 15] + EPSF)
                        + g_ctxmu[b * NPATCH + 15];
}

__global__ void assemble_kernel(float* __restrict__ out) {
    int idx = blockIdx.x * blockDim.x + threadIdx.x;
    int b = idx / 256, t = idx % 256;
    float m;
    if (t < 128) {
        m = 0.5f * (g_last[b * 128 + t] - g_last[(b + 32) * 128 + t]);
    } else {
        int o = t - 128;
        float va = g_no2[b * 128 + o]        * (g_nsg[b * 4 + 3] + EPSF)        + g_nmu[b * 4 + 3];
        float vb = g_no2[(b + 32) * 128 + o] * (g_nsg[(b + 32) * 4 + 3] + EPSF) + g_nmu[(b + 32) * 4 + 3];
        m = 0.5f * (va - vb);
    }
    if (g_ispos[b]) m = fmaxf(m, 0.f);
    out[idx] = m;
}

// ---------------- pointers bundle ----------------
struct DevPtrs {
    float *normed, *anorm, *hdd, *xn, *qkv, *Kc, *Vc, *no1, *no2;
    __nv_bfloat16 *xnh, *xnl, *atth, *attl, *h1h, *h1l;
    __nv_bfloat16 *qkvh, *qkvl, *woh, *wol, *w1h, *w1l, *w2h, *w2l;
};

// ---------------- full transformer forward ----------------
static void model_fwd_host(const DevPtrs& P, int T, int N, int C, int off,
                           const float* in_tok,
                           const float* W_in, const float* b_in, const float* ln1,
                           const float* ln2, const float* lnf,
                           float* nosel, int selStart, int selStep) {
    dim3 eg((DMODEL + BNs - 1) / BNs, (T + BMs - 1) / BMs), eb(16, 16);
    gemm_kernel<<<eg, eb>>>(in_tok, W_in, b_in, P.hdd, T, DMODEL, PATCH,
                            PATCH, DMODEL, DMODEL);
    for (int l = 0; l < NLAYER; l++) {
        ln_bf16_kernel<<<T, 256>>>(P.hdd, ln1 + (size_t)l * DMODEL, P.xnh, P.xnl);
        launch_bf16(P.xnh, P.xnl,
                    P.qkvh + (size_t)l * 3072 * 1024, P.qkvl + (size_t)l * 3072 * 1024,
                    P.qkv, nullptr, nullptr, T, 3 * DMODEL, DMODEL, 0);
        float* Kl = P.Kc + (size_t)l * NB * CMAX * DMODEL;
        float* Vl = P.Vc + (size_t)l * NB * CMAX * DMODEL;
        attn_kernel<<<NB * NH, dim3(32, N)>>>(P.qkv, Kl, Vl, P.atth, P.attl, N, C, off);
        launch_bf16(P.atth, P.attl,
                    P.woh + (size_t)l * 1024 * 1024, P.wol + (size_t)l * 1024 * 1024,
                    P.hdd, nullptr, nullptr, T, DMODEL, DMODEL, 1);
        ln_bf16_kernel<<<T, 256>>>(P.hdd, ln2 + (size_t)l * DMODEL, P.xnh, P.xnl);
        launch_bf16(P.xnh, P.xnl,
                    P.w1h + (size_t)l * 4096 * 1024, P.w1l + (size_t)l * 4096 * 1024,
                    nullptr, P.h1h, P.h1l, T, NDFF, DMODEL, 2);
        launch_bf16(P.h1h, P.h1l,
                    P.w2h + (size_t)l * 1024 * 4096, P.w2l + (size_t)l * 1024 * 4096,
                    P.hdd, nullptr, nullptr, T, DMODEL, NDFF, 1);
    }
    ln_kernel<<<T, 256>>>(P.hdd, lnf, P.xn);
    wout_kernel<<<8, 128>>>(P.xn, nosel, selStart, selStep);
}

// ---------------- entry ----------------
extern "C" void kernel_launch(void* const* d_in, const int* in_sizes, int n_in,
                              void* d_out, int out_size) {
    const float* x     = (const float*)d_in[0];
    const float* W_in  = (const float*)d_in[1];
    const float* b_in  = (const float*)d_in[2];
    const float* ln1_s = (const float*)d_in[3];
    const float* Wqkv  = (const float*)d_in[4];
    const float* Wo    = (const float*)d_in[5];
    const float* ln2_s = (const float*)d_in[6];
    const float* W1    = (const float*)d_in[7];
    const float* W2    = (const float*)d_in[8];
    const float* lnf_s = (const float*)d_in[9];
    const float* Wout  = (const float*)d_in[10];
    // d_in[11] = Wqs: provably unused for the median (channel-5) output

    DevPtrs P;
    cudaGetSymbolAddress((void**)&P.normed, g_normed);
    cudaGetSymbolAddress((void**)&P.anorm,  g_anorm);
    cudaGetSymbolAddress((void**)&P.hdd,    g_hdd);
    cudaGetSymbolAddress((void**)&P.xn,     g_xn);
    cudaGetSymbolAddress((void**)&P.qkv,    g_qkv);
    cudaGetSymbolAddress((void**)&P.Kc,     g_Kc);
    cudaGetSymbolAddress((void**)&P.Vc,     g_Vc);
    cudaGetSymbolAddress((void**)&P.no1,    g_no1);
    cudaGetSymbolAddress((void**)&P.no2,    g_no2);
    cudaGetSymbolAddress((void**)&P.xnh,    g_xnh);
    cudaGetSymbolAddress((void**)&P.xnl,    g_xnl);
    cudaGetSymbolAddress((void**)&P.atth,   g_atth);
    cudaGetSymbolAddress((void**)&P.attl,   g_attl);
    cudaGetSymbolAddress((void**)&P.h1h,    g_h1h);
    cudaGetSymbolAddress((void**)&P.h1l,    g_h1l);
    cudaGetSymbolAddress((void**)&P.qkvh,   g_Wqkvh);
    cudaGetSymbolAddress((void**)&P.qkvl,   g_Wqkvl);
    cudaGetSymbolAddress((void**)&P.woh,    g_Woh);
    cudaGetSymbolAddress((void**)&P.wol,    g_Wol);
    cudaGetSymbolAddress((void**)&P.w1h,    g_W1h);
    cudaGetSymbolAddress((void**)&P.w1l,    g_W1l);
    cudaGetSymbolAddress((void**)&P.w2h,    g_W2h);
    cudaGetSymbolAddress((void**)&P.w2l,    g_W2l);

    // Stage 0: weight transpose + bf16 split + Wout column extraction
    convT_kernel<<<dim3(3072 / 32, 1024 / 32, NLAYER), dim3(32, 8)>>>(Wqkv, P.qkvh, P.qkvl, 1024, 3072);
    convT_kernel<<<dim3(1024 / 32, 1024 / 32, NLAYER), dim3(32, 8)>>>(Wo,   P.woh,  P.wol,  1024, 1024);
    convT_kernel<<<dim3(4096 / 32, 1024 / 32, NLAYER), dim3(32, 8)>>>(W1,   P.w1h,  P.w1l,  1024, 4096);
    convT_kernel<<<dim3(1024 / 32, 4096 / 32, NLAYER), dim3(32, 8)>>>(W2,   P.w2h,  P.w2l,  4096, 1024);
    wsel_kernel<<<512, 256>>>(Wout);

    // Stage A: running stats + normalization for x and -x (batch 64)
    stats_kernel<<<NB, 32>>>(x);

    // Stage B: prefill (C=16, offset 0)
    model_fwd_host(P, T1, NPATCH, 16, 0, P.normed,
                   W_in, b_in, ln1_s, ln2_s, lnf_s,
                   P.no1, /*selStart=*/15, /*selStep=*/16);
    revin_last_kernel<<<NB, 128>>>();

    // Stage C: AR stats + one autoregressive step (C=20, offset 16)
    ar_stats_kernel<<<NB, 32>>>();
    model_fwd_host(P, T2, 4, 20, 16, P.anorm,
                   W_in, b_in, ln1_s, ln2_s, lnf_s,
                   P.no2, /*selStart=*/3, /*selStep=*/4);

    // Stage D: combine x / -x, clamp, write [32,256]
    assemble_kernel<<<32, 256>>>((float*)d_out);
}